// round 12
// baseline (speedup 1.0000x reference)
#include <cuda_runtime.h>
#include <cuda_fp16.h>
#include <cstdint>
#include <math.h>

namespace {
constexpr int NTOK = 8192;
constexpr int D    = 1024;
constexpr int HD   = 512;
constexpr int NE   = 8;
constexpr int BM = 128, BN = 256;
constexpr int CAP  = 17408;            // 2*NTOK + per-expert pad to 128
}

__device__ int   g_counts[NE];
__device__ int   g_offsets[NE + 1];
__device__ int   g_cursor[NE];
__device__ int   g_perm[CAP];
__device__ float g_wgt[CAP];
__device__ int   g_tok_e[NTOK * 2];
__device__ float g_tok_w[NTOK * 2];

// fp16 operands, single plane. Weights [K,N] row-major.
__device__ __align__(16) __half g_Xh[NTOK * D];
__device__ __align__(16) __half g_W1h[D * HD];
__device__ __align__(16) __half g_W2h[HD * D];
__device__ __align__(16) __half g_r1h[NE * D * HD];
__device__ __align__(16) __half g_r2h[NE * HD * D];
__device__ __align__(16) __half g_Hsh[NTOK * HD];
__device__ __align__(16) __half g_Hrh[(size_t)CAP * HD];

// ---------------- routing / bookkeeping ----------------

__global__ void init_kernel() {
    int i = blockIdx.x * blockDim.x + threadIdx.x;
    if (i < NE) g_counts[i] = 0;
    if (i < CAP) { g_perm[i] = 0; g_wgt[i] = 0.0f; }
}

__global__ void routing_kernel(const float* __restrict__ X,
                               const float* __restrict__ RW,
                               const float* __restrict__ EB) {
    int warp = (blockIdx.x * blockDim.x + threadIdx.x) >> 5;
    int lane = threadIdx.x & 31;
    if (warp >= NTOK) return;
    const float* x = X + (size_t)warp * D;
    float acc[NE];
#pragma unroll
    for (int e = 0; e < NE; e++) acc[e] = 0.0f;
    for (int k = lane; k < D; k += 32) {
        float xv = x[k];
#pragma unroll
        for (int e = 0; e < NE; e++) acc[e] = fmaf(xv, RW[e * D + k], acc[e]);
    }
#pragma unroll
    for (int e = 0; e < NE; e++) {
#pragma unroll
        for (int o = 16; o > 0; o >>= 1)
            acc[e] += __shfl_down_sync(0xffffffffu, acc[e], o);
    }
    if (lane == 0) {
        float act[NE];
#pragma unroll
        for (int e = 0; e < NE; e++) {
            float l = acc[e] + EB[e];
            float sp = (l > 0.0f) ? (l + log1pf(expf(-l))) : log1pf(expf(l));
            act[e] = sqrtf(sp);
        }
        int i0 = 0;
#pragma unroll
        for (int e = 1; e < NE; e++) if (act[e] > act[i0]) i0 = e;
        int i1 = (i0 == 0) ? 1 : 0;
#pragma unroll
        for (int e = 0; e < NE; e++)
            if (e != i0 && act[e] > act[i1]) i1 = e;
        g_tok_e[2 * warp + 0] = i0; g_tok_w[2 * warp + 0] = act[i0];
        g_tok_e[2 * warp + 1] = i1; g_tok_w[2 * warp + 1] = act[i1];
        atomicAdd(&g_counts[i0], 1);
        atomicAdd(&g_counts[i1], 1);
    }
}

__global__ void prefix_kernel() {
    if (threadIdx.x == 0 && blockIdx.x == 0) {
        int off = 0;
        for (int e = 0; e < NE; e++) {
            g_offsets[e] = off;
            g_cursor[e]  = off;
            off += ((g_counts[e] + BM - 1) / BM) * BM;
        }
        g_offsets[NE] = off;
    }
}

__global__ void scatter_kernel() {
    int i = blockIdx.x * blockDim.x + threadIdx.x;
    if (i >= NTOK * 2) return;
    int e = g_tok_e[i];
    int slot = atomicAdd(&g_cursor[e], 1);
    g_perm[slot] = i >> 1;
    g_wgt[slot]  = g_tok_w[i];
}

// fp32 -> fp16
__global__ void cvt_kernel(const float* __restrict__ src, int n, int sel) {
    int i = (blockIdx.x * blockDim.x + threadIdx.x) * 2;
    if (i >= n) return;
    float2 v = *reinterpret_cast<const float2*>(src + i);
    __half* p;
    switch (sel) {
        case 0:  p = g_Xh;  break;
        case 1:  p = g_W1h; break;
        case 2:  p = g_W2h; break;
        case 3:  p = g_r1h; break;
        default: p = g_r2h; break;
    }
    *reinterpret_cast<__half2*>(p + i) =
        __halves2half2(__float2half(v.x), __float2half(v.y));
}

__device__ __forceinline__ float silu(float v) { return v / (1.0f + expf(-v)); }

// ---------------- mma helpers ----------------

__device__ __forceinline__ void ldsm4(uint32_t (&r)[4], uint32_t addr) {
    asm volatile("ldmatrix.sync.aligned.m8n8.x4.shared.b16 {%0,%1,%2,%3}, [%4];\n"
        : "=r"(r[0]), "=r"(r[1]), "=r"(r[2]), "=r"(r[3]) : "r"(addr));
}
__device__ __forceinline__ void ldsm4t(uint32_t (&r)[4], uint32_t addr) {
    asm volatile("ldmatrix.sync.aligned.m8n8.x4.trans.shared.b16 {%0,%1,%2,%3}, [%4];\n"
        : "=r"(r[0]), "=r"(r[1]), "=r"(r[2]), "=r"(r[3]) : "r"(addr));
}
__device__ __forceinline__ void mma_f16(float (&c)[4], const uint32_t (&a)[4],
                                        uint32_t b0, uint32_t b1) {
    asm volatile(
        "mma.sync.aligned.m16n8k16.row.col.f32.f16.f16.f32 "
        "{%0,%1,%2,%3}, {%4,%5,%6,%7}, {%8,%9}, {%0,%1,%2,%3};\n"
        : "+f"(c[0]), "+f"(c[1]), "+f"(c[2]), "+f"(c[3])
        : "r"(a[0]), "r"(a[1]), "r"(a[2]), "r"(a[3]), "r"(b0), "r"(b1));
}

// MODE 0: Hs = silu(X@W1+b)      MODE 1: Hr = silu(X[perm]@rW1[e]+b)
// MODE 2: out = Hs@W2+b (store)  MODE 3: out[tok] += w*(Hr@rW2[e]+b) (atomic)
template <int MODE, int KDIM, int NDIM>
__device__ __forceinline__ void gemm_body(const float* __restrict__ bias,
                                          float* __restrict__ out) {
    __shared__ __align__(16) __half sA[2][128][24];    // [stage][m][k]
    __shared__ __align__(16) __half sB[2][16][264];    // [stage][k][n] pad 264
    __shared__ int   s_row[128];
    __shared__ int   s_tok[128];
    __shared__ float s_w[128];

    const int tid = threadIdx.x;
    const int rowTile = blockIdx.y * BM;
    const int colTile = blockIdx.x * BN;

    const __half* Wp;
    const float* bb = bias;
    if constexpr (MODE == 0)      Wp = g_W1h;
    else if constexpr (MODE == 2) Wp = g_W2h;
    else {
        int e = 0;
#pragma unroll
        for (int i = 1; i < NE; i++) if (rowTile >= g_offsets[i]) e = i;
        size_t off = (size_t)e * KDIM * NDIM;
        if constexpr (MODE == 1) Wp = g_r1h + off;
        else                     Wp = g_r2h + off;
        bb = bias + e * NDIM;
    }
    const __half* Ag;
    if constexpr (MODE <= 1)      Ag = g_Xh;
    else if constexpr (MODE == 2) Ag = g_Hsh;
    else                          Ag = g_Hrh;

    if (tid < BM) {
        int r = rowTile + tid;
        if constexpr (MODE == 1) s_row[tid] = g_perm[r];
        else                     s_row[tid] = r;
        if constexpr (MODE == 3) { s_tok[tid] = g_perm[r]; s_w[tid] = g_wgt[r]; }
    }
    __syncthreads();

    const int lane = tid & 31, warp = tid >> 5;
    const int wm = warp >> 2;     // 0..1 -> 64 rows each
    const int wn = warp & 3;      // 0..3 -> 64 cols each

    // staging: A 128x16 (one uint4/thread), B 16x256 (two uint4/thread)
    const int aR = tid >> 1,  aC = (tid & 1) * 8;
    const int bR = tid >> 4,  bC = (tid & 15) * 16;
    const size_t arow = (size_t)s_row[aR];
    const __half* Ap = Ag + arow * KDIM + aC;
    const __half* Bp = Wp + (size_t)bR * NDIM + colTile + bC;

    // ldmatrix lane addresses
    uint32_t sAaddr = (uint32_t)__cvta_generic_to_shared(
        &sA[0][wm * 64 + (lane & 15)][(lane >> 4) * 8]);
    uint32_t sBaddr = (uint32_t)__cvta_generic_to_shared(
        &sB[0][(lane & 7) + ((lane >> 3) & 1) * 8][wn * 64 + (lane >> 4) * 8]);
    constexpr uint32_t A_STAGE = 128 * 24 * 2;     // 6144
    constexpr uint32_t B_STAGE = 16 * 264 * 2;     // 8448

    float acc[4][8][4] = {};
    uint4 rA, rB0, rB1;

    // prologue: stage 0
    rA  = *reinterpret_cast<const uint4*>(Ap);
    rB0 = *reinterpret_cast<const uint4*>(Bp);
    rB1 = *reinterpret_cast<const uint4*>(Bp + 8);
    *reinterpret_cast<uint4*>(&sA[0][aR][aC])     = rA;
    *reinterpret_cast<uint4*>(&sB[0][bR][bC])     = rB0;
    *reinterpret_cast<uint4*>(&sB[0][bR][bC + 8]) = rB1;
    __syncthreads();

    int st = 0;
    for (int kt = 0; kt < KDIM; kt += 16) {
        const bool more = (kt + 16 < KDIM);
        if (more) {
            rA  = *reinterpret_cast<const uint4*>(Ap + kt + 16);
            rB0 = *reinterpret_cast<const uint4*>(Bp + (size_t)(kt + 16) * NDIM);
            rB1 = *reinterpret_cast<const uint4*>(Bp + (size_t)(kt + 16) * NDIM + 8);
        }
        uint32_t aF[4][4], bF[4][4];
#pragma unroll
        for (int mi = 0; mi < 4; mi++)
            ldsm4(aF[mi], sAaddr + st * A_STAGE + mi * (16 * 24 * 2));
#pragma unroll
        for (int p = 0; p < 4; p++)
            ldsm4t(bF[p], sBaddr + st * B_STAGE + p * (16 * 2));
#pragma unroll
        for (int mi = 0; mi < 4; mi++)
#pragma unroll
            for (int ni = 0; ni < 8; ni++) {
                const int p = ni >> 1, q = (ni & 1) * 2;
                mma_f16(acc[mi][ni], aF[mi], bF[p][q], bF[p][q + 1]);
            }
        if (more) {
            *reinterpret_cast<uint4*>(&sA[st ^ 1][aR][aC])     = rA;
            *reinterpret_cast<uint4*>(&sB[st ^ 1][bR][bC])     = rB0;
            *reinterpret_cast<uint4*>(&sB[st ^ 1][bR][bC + 8]) = rB1;
        }
        st ^= 1;
        __syncthreads();
    }

    // epilogue
    const int r0 = lane >> 2, c0 = (lane & 3) * 2;
#pragma unroll
    for (int mi = 0; mi < 4; mi++) {
#pragma unroll
        for (int rr = 0; rr < 2; rr++) {
            const int m = wm * 64 + mi * 16 + r0 + rr * 8;
            const int grow = rowTile + m;
#pragma unroll
            for (int ni = 0; ni < 8; ni++) {
                const int col = colTile + wn * 64 + ni * 8 + c0;
                float v0 = acc[mi][ni][rr * 2 + 0] + bb[col];
                float v1 = acc[mi][ni][rr * 2 + 1] + bb[col + 1];
                if constexpr (MODE <= 1) {
                    v0 = silu(v0); v1 = silu(v1);
                    __half* H = (MODE == 0 ? g_Hsh : g_Hrh);
                    *reinterpret_cast<__half2*>(H + (size_t)grow * NDIM + col)
                        = __halves2half2(__float2half(v0), __float2half(v1));
                } else if constexpr (MODE == 2) {
                    *reinterpret_cast<float2*>(out + (size_t)grow * NDIM + col)
                        = make_float2(v0, v1);
                } else {
                    const float w = s_w[m];
                    float* dst = out + (size_t)s_tok[m] * NDIM + col;
                    atomicAdd(dst + 0, w * v0);
                    atomicAdd(dst + 1, w * v1);
                }
            }
        }
    }
}

__global__ void __launch_bounds__(256, 1) gemm_m0(const float* __restrict__ bias) {
    gemm_body<0, D, HD>(bias, nullptr);
}
__global__ void __launch_bounds__(256, 1) gemm_m1(const float* __restrict__ bias) {
    gemm_body<1, D, HD>(bias, nullptr);
}
__global__ void __launch_bounds__(256, 1) gemm_m2(const float* __restrict__ bias,
                                                  float* __restrict__ out) {
    gemm_body<2, HD, D>(bias, out);
}
__global__ void __launch_bounds__(256, 1) gemm_m3(const float* __restrict__ bias,
                                                  float* __restrict__ out) {
    gemm_body<3, HD, D>(bias, out);
}

extern "C" void kernel_launch(void* const* d_in, const int* in_sizes, int n_in,
                              void* d_out, int out_size) {
    (void)in_sizes; (void)n_in; (void)out_size;
    const float* X   = (const float*)d_in[0];
    const float* RW  = (const float*)d_in[1];
    const float* EB  = (const float*)d_in[2];
    const float* sW1 = (const float*)d_in[3];
    const float* sb1 = (const float*)d_in[4];
    const float* sW2 = (const float*)d_in[5];
    const float* sb2 = (const float*)d_in[6];
    const float* rW1 = (const float*)d_in[7];
    const float* rb1 = (const float*)d_in[8];
    const float* rW2 = (const float*)d_in[9];
    const float* rb2 = (const float*)d_in[10];
    float* out = (float*)d_out;

    init_kernel<<<(CAP + 255) / 256, 256>>>();
    routing_kernel<<<NTOK / 8, 256>>>(X, RW, EB);
    prefix_kernel<<<1, 32>>>();
    scatter_kernel<<<(NTOK * 2) / 256, 256>>>();

    cvt_kernel<<<(NTOK * D / 2 + 255) / 256, 256>>>(X, NTOK * D, 0);
    cvt_kernel<<<(D * HD / 2 + 255) / 256, 256>>>(sW1, D * HD, 1);
    cvt_kernel<<<(HD * D / 2 + 255) / 256, 256>>>(sW2, HD * D, 2);
    cvt_kernel<<<(NE * D * HD / 2 + 255) / 256, 256>>>(rW1, NE * D * HD, 3);
    cvt_kernel<<<(NE * HD * D / 2 + 255) / 256, 256>>>(rW2, NE * HD * D, 4);

    gemm_m0<<<dim3(HD / BN, NTOK / BM), 256>>>(sb1);
    gemm_m1<<<dim3(HD / BN, CAP / BM), 256>>>(rb1);
    gemm_m2<<<dim3(D / BN, NTOK / BM), 256>>>(sb2, out);
    gemm_m3<<<dim3(D / BN, CAP / BM), 256>>>(rb2, out);
}

// round 13
// speedup vs baseline: 1.2750x; 1.2750x over previous
#include <cuda_runtime.h>
#include <cuda_fp16.h>
#include <cstdint>
#include <math.h>

namespace {
constexpr int NTOK = 8192;
constexpr int D    = 1024;
constexpr int HD   = 512;
constexpr int NE   = 8;
constexpr int BM = 128, BN = 128;
constexpr int KT = 32;                 // k-tile per stage
constexpr int CAP  = 17408;            // 2*NTOK + per-expert pad to 128
}

__device__ int   g_counts[NE];
__device__ int   g_offsets[NE + 1];
__device__ int   g_cursor[NE];
__device__ int   g_perm[CAP];
__device__ float g_wgt[CAP];
__device__ int   g_tok_e[NTOK * 2];
__device__ float g_tok_w[NTOK * 2];

// fp16 operands, single plane. Weights [K,N] row-major.
__device__ __align__(16) __half g_Xh[NTOK * D];
__device__ __align__(16) __half g_W1h[D * HD];
__device__ __align__(16) __half g_W2h[HD * D];
__device__ __align__(16) __half g_r1h[NE * D * HD];
__device__ __align__(16) __half g_r2h[NE * HD * D];
__device__ __align__(16) __half g_Hsh[NTOK * HD];
__device__ __align__(16) __half g_Hrh[(size_t)CAP * HD];

// ---------------- routing / bookkeeping ----------------

__global__ void init_kernel() {
    int i = blockIdx.x * blockDim.x + threadIdx.x;
    if (i < NE) g_counts[i] = 0;
    if (i < CAP) { g_perm[i] = 0; g_wgt[i] = 0.0f; }
}

__global__ void routing_kernel(const float* __restrict__ X,
                               const float* __restrict__ RW,
                               const float* __restrict__ EB) {
    int warp = (blockIdx.x * blockDim.x + threadIdx.x) >> 5;
    int lane = threadIdx.x & 31;
    if (warp >= NTOK) return;
    const float* x = X + (size_t)warp * D;
    float acc[NE];
#pragma unroll
    for (int e = 0; e < NE; e++) acc[e] = 0.0f;
    for (int k = lane; k < D; k += 32) {
        float xv = x[k];
#pragma unroll
        for (int e = 0; e < NE; e++) acc[e] = fmaf(xv, RW[e * D + k], acc[e]);
    }
#pragma unroll
    for (int e = 0; e < NE; e++) {
#pragma unroll
        for (int o = 16; o > 0; o >>= 1)
            acc[e] += __shfl_down_sync(0xffffffffu, acc[e], o);
    }
    if (lane == 0) {
        float act[NE];
#pragma unroll
        for (int e = 0; e < NE; e++) {
            float l = acc[e] + EB[e];
            float sp = (l > 0.0f) ? (l + log1pf(expf(-l))) : log1pf(expf(l));
            act[e] = sqrtf(sp);
        }
        int i0 = 0;
#pragma unroll
        for (int e = 1; e < NE; e++) if (act[e] > act[i0]) i0 = e;
        int i1 = (i0 == 0) ? 1 : 0;
#pragma unroll
        for (int e = 0; e < NE; e++)
            if (e != i0 && act[e] > act[i1]) i1 = e;
        g_tok_e[2 * warp + 0] = i0; g_tok_w[2 * warp + 0] = act[i0];
        g_tok_e[2 * warp + 1] = i1; g_tok_w[2 * warp + 1] = act[i1];
        atomicAdd(&g_counts[i0], 1);
        atomicAdd(&g_counts[i1], 1);
    }
}

__global__ void prefix_kernel() {
    if (threadIdx.x == 0 && blockIdx.x == 0) {
        int off = 0;
        for (int e = 0; e < NE; e++) {
            g_offsets[e] = off;
            g_cursor[e]  = off;
            off += ((g_counts[e] + BM - 1) / BM) * BM;
        }
        g_offsets[NE] = off;
    }
}

__global__ void scatter_kernel() {
    int i = blockIdx.x * blockDim.x + threadIdx.x;
    if (i >= NTOK * 2) return;
    int e = g_tok_e[i];
    int slot = atomicAdd(&g_cursor[e], 1);
    g_perm[slot] = i >> 1;
    g_wgt[slot]  = g_tok_w[i];
}

// fp32 -> fp16
__global__ void cvt_kernel(const float* __restrict__ src, int n, int sel) {
    int i = (blockIdx.x * blockDim.x + threadIdx.x) * 2;
    if (i >= n) return;
    float2 v = *reinterpret_cast<const float2*>(src + i);
    __half* p;
    switch (sel) {
        case 0:  p = g_Xh;  break;
        case 1:  p = g_W1h; break;
        case 2:  p = g_W2h; break;
        case 3:  p = g_r1h; break;
        default: p = g_r2h; break;
    }
    *reinterpret_cast<__half2*>(p + i) =
        __halves2half2(__float2half(v.x), __float2half(v.y));
}

__device__ __forceinline__ float silu(float v) { return v / (1.0f + expf(-v)); }

// ---------------- mma helpers ----------------

__device__ __forceinline__ void ldsm4(uint32_t (&r)[4], uint32_t addr) {
    asm volatile("ldmatrix.sync.aligned.m8n8.x4.shared.b16 {%0,%1,%2,%3}, [%4];\n"
        : "=r"(r[0]), "=r"(r[1]), "=r"(r[2]), "=r"(r[3]) : "r"(addr));
}
__device__ __forceinline__ void ldsm4t(uint32_t (&r)[4], uint32_t addr) {
    asm volatile("ldmatrix.sync.aligned.m8n8.x4.trans.shared.b16 {%0,%1,%2,%3}, [%4];\n"
        : "=r"(r[0]), "=r"(r[1]), "=r"(r[2]), "=r"(r[3]) : "r"(addr));
}
__device__ __forceinline__ void mma_f16(float (&c)[4], const uint32_t (&a)[4],
                                        uint32_t b0, uint32_t b1) {
    asm volatile(
        "mma.sync.aligned.m16n8k16.row.col.f32.f16.f16.f32 "
        "{%0,%1,%2,%3}, {%4,%5,%6,%7}, {%8,%9}, {%0,%1,%2,%3};\n"
        : "+f"(c[0]), "+f"(c[1]), "+f"(c[2]), "+f"(c[3])
        : "r"(a[0]), "r"(a[1]), "r"(a[2]), "r"(a[3]), "r"(b0), "r"(b1));
}

// MODE 0: Hs = silu(X@W1+b)      MODE 1: Hr = silu(X[perm]@rW1[e]+b)
// MODE 2: out = Hs@W2+b (store)  MODE 3: out[tok] += w*(Hr@rW2[e]+b) (atomic)
template <int MODE, int KDIM, int NDIM>
__device__ __forceinline__ void gemm_body(const float* __restrict__ bias,
                                          float* __restrict__ out) {
    __shared__ __align__(16) __half sA[2][128][40];    // [stage][m][k32 + pad8]
    __shared__ __align__(16) __half sB[2][32][136];    // [stage][k32][n + pad8]
    __shared__ int   s_row[128];
    __shared__ int   s_tok[128];
    __shared__ float s_w[128];

    const int tid = threadIdx.x;
    const int rowTile = blockIdx.y * BM;
    const int colTile = blockIdx.x * BN;

    const __half* Wp;
    const float* bb = bias;
    if constexpr (MODE == 0)      Wp = g_W1h;
    else if constexpr (MODE == 2) Wp = g_W2h;
    else {
        int e = 0;
#pragma unroll
        for (int i = 1; i < NE; i++) if (rowTile >= g_offsets[i]) e = i;
        size_t off = (size_t)e * KDIM * NDIM;
        if constexpr (MODE == 1) Wp = g_r1h + off;
        else                     Wp = g_r2h + off;
        bb = bias + e * NDIM;
    }
    const __half* Ag;
    if constexpr (MODE <= 1)      Ag = g_Xh;
    else if constexpr (MODE == 2) Ag = g_Hsh;
    else                          Ag = g_Hrh;

    if (tid < BM) {
        int r = rowTile + tid;
        if constexpr (MODE == 1) s_row[tid] = g_perm[r];
        else                     s_row[tid] = r;
        if constexpr (MODE == 3) { s_tok[tid] = g_perm[r]; s_w[tid] = g_wgt[r]; }
    }
    __syncthreads();

    const int lane = tid & 31, warp = tid >> 5;
    const int wm = warp >> 2;     // 0..1 -> 64 rows each
    const int wn = warp & 3;      // 0..3 -> 32 cols each

    // staging: A 128 rows x 32 halfs (2 vectors/thread: rows r0, r0+64),
    //          B 32 rows x 128 halfs (2 vectors/thread: rows r, r+16)
    const int aR0 = tid >> 2,  aC = (tid & 3) * 8;    // rows 0..63
    const int bR0 = tid >> 4,  bC = (tid & 15) * 8;   // rows 0..15
    const __half* Ap0 = Ag + (size_t)s_row[aR0] * KDIM + aC;
    const __half* Ap1 = Ag + (size_t)s_row[aR0 + 64] * KDIM + aC;
    const __half* Bp0 = Wp + (size_t)bR0 * NDIM + colTile + bC;
    const __half* Bp1 = Wp + (size_t)(bR0 + 16) * NDIM + colTile + bC;

    // ldmatrix lane addresses (stage 0, k-slice 0)
    uint32_t sAaddr = (uint32_t)__cvta_generic_to_shared(
        &sA[0][wm * 64 + (lane & 15)][(lane >> 4) * 8]);
    uint32_t sBaddr = (uint32_t)__cvta_generic_to_shared(
        &sB[0][(lane & 7) + ((lane >> 3) & 1) * 8][wn * 32 + (lane >> 4) * 8]);
    constexpr uint32_t A_STAGE = 128 * 40 * 2;     // 10240
    constexpr uint32_t B_STAGE = 32 * 136 * 2;     // 8704
    constexpr uint32_t A_ROW   = 40 * 2;
    constexpr uint32_t B_ROW   = 136 * 2;

    float acc[4][4][4] = {};
    uint4 rA0, rA1, rB0, rB1;

    // prologue: stage 0
    rA0 = *reinterpret_cast<const uint4*>(Ap0);
    rA1 = *reinterpret_cast<const uint4*>(Ap1);
    rB0 = *reinterpret_cast<const uint4*>(Bp0);
    rB1 = *reinterpret_cast<const uint4*>(Bp1);
    *reinterpret_cast<uint4*>(&sA[0][aR0][aC])      = rA0;
    *reinterpret_cast<uint4*>(&sA[0][aR0 + 64][aC]) = rA1;
    *reinterpret_cast<uint4*>(&sB[0][bR0][bC])      = rB0;
    *reinterpret_cast<uint4*>(&sB[0][bR0 + 16][bC]) = rB1;
    __syncthreads();

    constexpr int NKT = KDIM / KT;
    int st = 0;
    for (int i = 0; i < NKT; i++) {
        const bool more = (i + 1 < NKT);
        if (more) {
            const int kt = (i + 1) * KT;
            rA0 = *reinterpret_cast<const uint4*>(Ap0 + kt);
            rA1 = *reinterpret_cast<const uint4*>(Ap1 + kt);
            rB0 = *reinterpret_cast<const uint4*>(Bp0 + (size_t)kt * NDIM);
            rB1 = *reinterpret_cast<const uint4*>(Bp1 + (size_t)kt * NDIM);
        }
#pragma unroll
        for (int kk = 0; kk < 2; kk++) {           // two k16 slices
            uint32_t aF[4][4], bF[2][4];
#pragma unroll
            for (int mi = 0; mi < 4; mi++)
                ldsm4(aF[mi], sAaddr + st * A_STAGE + kk * 32 + mi * (16 * A_ROW));
#pragma unroll
            for (int p = 0; p < 2; p++)
                ldsm4t(bF[p], sBaddr + st * B_STAGE + kk * (16 * B_ROW) + p * 32);
#pragma unroll
            for (int mi = 0; mi < 4; mi++)
#pragma unroll
                for (int ni = 0; ni < 4; ni++) {
                    const int p = ni >> 1, q = (ni & 1) * 2;
                    mma_f16(acc[mi][ni], aF[mi], bF[p][q], bF[p][q + 1]);
                }
        }
        if (more) {
            *reinterpret_cast<uint4*>(&sA[st ^ 1][aR0][aC])      = rA0;
            *reinterpret_cast<uint4*>(&sA[st ^ 1][aR0 + 64][aC]) = rA1;
            *reinterpret_cast<uint4*>(&sB[st ^ 1][bR0][bC])      = rB0;
            *reinterpret_cast<uint4*>(&sB[st ^ 1][bR0 + 16][bC]) = rB1;
        }
        st ^= 1;
        __syncthreads();
    }

    // epilogue
    const int r0 = lane >> 2, c0 = (lane & 3) * 2;
#pragma unroll
    for (int mi = 0; mi < 4; mi++) {
#pragma unroll
        for (int rr = 0; rr < 2; rr++) {
            const int m = wm * 64 + mi * 16 + r0 + rr * 8;
            const int grow = rowTile + m;
#pragma unroll
            for (int ni = 0; ni < 4; ni++) {
                const int col = colTile + wn * 32 + ni * 8 + c0;
                float v0 = acc[mi][ni][rr * 2 + 0] + bb[col];
                float v1 = acc[mi][ni][rr * 2 + 1] + bb[col + 1];
                if constexpr (MODE <= 1) {
                    v0 = silu(v0); v1 = silu(v1);
                    __half* H = (MODE == 0 ? g_Hsh : g_Hrh);
                    *reinterpret_cast<__half2*>(H + (size_t)grow * NDIM + col)
                        = __halves2half2(__float2half(v0), __float2half(v1));
                } else if constexpr (MODE == 2) {
                    *reinterpret_cast<float2*>(out + (size_t)grow * NDIM + col)
                        = make_float2(v0, v1);
                } else {
                    const float w = s_w[m];
                    float* dst = out + (size_t)s_tok[m] * NDIM + col;
                    atomicAdd(dst + 0, w * v0);
                    atomicAdd(dst + 1, w * v1);
                }
            }
        }
    }
}

__global__ void __launch_bounds__(256, 2) gemm_m0(const float* __restrict__ bias) {
    gemm_body<0, D, HD>(bias, nullptr);
}
__global__ void __launch_bounds__(256, 2) gemm_m1(const float* __restrict__ bias) {
    gemm_body<1, D, HD>(bias, nullptr);
}
__global__ void __launch_bounds__(256, 2) gemm_m2(const float* __restrict__ bias,
                                                  float* __restrict__ out) {
    gemm_body<2, HD, D>(bias, out);
}
__global__ void __launch_bounds__(256, 2) gemm_m3(const float* __restrict__ bias,
                                                  float* __restrict__ out) {
    gemm_body<3, HD, D>(bias, out);
}

extern "C" void kernel_launch(void* const* d_in, const int* in_sizes, int n_in,
                              void* d_out, int out_size) {
    (void)in_sizes; (void)n_in; (void)out_size;
    const float* X   = (const float*)d_in[0];
    const float* RW  = (const float*)d_in[1];
    const float* EB  = (const float*)d_in[2];
    const float* sW1 = (const float*)d_in[3];
    const float* sb1 = (const float*)d_in[4];
    const float* sW2 = (const float*)d_in[5];
    const float* sb2 = (const float*)d_in[6];
    const float* rW1 = (const float*)d_in[7];
    const float* rb1 = (const float*)d_in[8];
    const float* rW2 = (const float*)d_in[9];
    const float* rb2 = (const float*)d_in[10];
    float* out = (float*)d_out;

    init_kernel<<<(CAP + 255) / 256, 256>>>();
    routing_kernel<<<NTOK / 8, 256>>>(X, RW, EB);
    prefix_kernel<<<1, 32>>>();
    scatter_kernel<<<(NTOK * 2) / 256, 256>>>();

    cvt_kernel<<<(NTOK * D / 2 + 255) / 256, 256>>>(X, NTOK * D, 0);
    cvt_kernel<<<(D * HD / 2 + 255) / 256, 256>>>(sW1, D * HD, 1);
    cvt_kernel<<<(HD * D / 2 + 255) / 256, 256>>>(sW2, HD * D, 2);
    cvt_kernel<<<(NE * D * HD / 2 + 255) / 256, 256>>>(rW1, NE * D * HD, 3);
    cvt_kernel<<<(NE * HD * D / 2 + 255) / 256, 256>>>(rW2, NE * HD * D, 4);

    gemm_m0<<<dim3(HD / BN, NTOK / BM), 256>>>(sb1);
    gemm_m1<<<dim3(HD / BN, CAP / BM), 256>>>(rb1);
    gemm_m2<<<dim3(D / BN, NTOK / BM), 256>>>(sb2, out);
    gemm_m3<<<dim3(D / BN, CAP / BM), 256>>>(rb2, out);
}

// round 15
// speedup vs baseline: 1.3780x; 1.0808x over previous
#include <cuda_runtime.h>
#include <cuda_fp16.h>
#include <cstdint>
#include <math.h>

namespace {
constexpr int NTOK = 8192;
constexpr int D    = 1024;
constexpr int HD   = 512;
constexpr int NE   = 8;
constexpr int BM = 128, BN = 128;
constexpr int KT = 32;                 // k-tile per stage
constexpr int CAP  = 17408;            // 2*NTOK + per-expert pad to 128
constexpr int YT_S = NTOK / BM;        // 64 shared row-tiles
constexpr int YT_R = CAP / BM;         // 136 routed row-tiles
}

__device__ int   g_counts[NE];
__device__ int   g_offsets[NE + 1];
__device__ int   g_cursor[NE];
__device__ int   g_perm[CAP];
__device__ float g_wgt[CAP];
__device__ int   g_tok_e[NTOK * 2];
__device__ float g_tok_w[NTOK * 2];

// fp16 operands, single plane. Weights [K,N] row-major.
__device__ __align__(16) __half g_Xh[NTOK * D];
__device__ __align__(16) __half g_W1h[D * HD];
__device__ __align__(16) __half g_W2h[HD * D];
__device__ __align__(16) __half g_r1h[NE * D * HD];
__device__ __align__(16) __half g_r2h[NE * HD * D];
__device__ __align__(16) __half g_Hsh[NTOK * HD];
__device__ __align__(16) __half g_Hrh[(size_t)CAP * HD];

// shared-memory tile block (single allocation per CTA)
struct SmemTiles {
    __align__(16) __half sA[2][128][40];   // [stage][m][k32 + pad8]
    __align__(16) __half sB[2][32][136];   // [stage][k32][n + pad8]
    int   s_row[128];
    int   s_tok[128];
    float s_w[128];
};

// ---------------- routing / bookkeeping ----------------

__global__ void init_kernel() {
    int i = blockIdx.x * blockDim.x + threadIdx.x;
    if (i < NE) g_counts[i] = 0;
    if (i < CAP) { g_perm[i] = 0; g_wgt[i] = 0.0f; }
}

// routing + X->fp16 conversion fused (X read once)
__global__ void routing_kernel(const float* __restrict__ X,
                               const float* __restrict__ RW,
                               const float* __restrict__ EB) {
    int warp = (blockIdx.x * blockDim.x + threadIdx.x) >> 5;
    int lane = threadIdx.x & 31;
    if (warp >= NTOK) return;
    const float* x = X + (size_t)warp * D;
    __half* xo = g_Xh + (size_t)warp * D;
    float acc[NE];
#pragma unroll
    for (int e = 0; e < NE; e++) acc[e] = 0.0f;
    for (int k = lane; k < D; k += 32) {
        float xv = x[k];
        xo[k] = __float2half(xv);
#pragma unroll
        for (int e = 0; e < NE; e++) acc[e] = fmaf(xv, RW[e * D + k], acc[e]);
    }
#pragma unroll
    for (int e = 0; e < NE; e++) {
#pragma unroll
        for (int o = 16; o > 0; o >>= 1)
            acc[e] += __shfl_down_sync(0xffffffffu, acc[e], o);
    }
    if (lane == 0) {
        float act[NE];
#pragma unroll
        for (int e = 0; e < NE; e++) {
            float l = acc[e] + EB[e];
            float sp = (l > 0.0f) ? (l + log1pf(expf(-l))) : log1pf(expf(l));
            act[e] = sqrtf(sp);
        }
        int i0 = 0;
#pragma unroll
        for (int e = 1; e < NE; e++) if (act[e] > act[i0]) i0 = e;
        int i1 = (i0 == 0) ? 1 : 0;
#pragma unroll
        for (int e = 0; e < NE; e++)
            if (e != i0 && act[e] > act[i1]) i1 = e;
        g_tok_e[2 * warp + 0] = i0; g_tok_w[2 * warp + 0] = act[i0];
        g_tok_e[2 * warp + 1] = i1; g_tok_w[2 * warp + 1] = act[i1];
        atomicAdd(&g_counts[i0], 1);
        atomicAdd(&g_counts[i1], 1);
    }
}

__global__ void prefix_kernel() {
    if (threadIdx.x == 0 && blockIdx.x == 0) {
        int off = 0;
        for (int e = 0; e < NE; e++) {
            g_offsets[e] = off;
            g_cursor[e]  = off;
            off += ((g_counts[e] + BM - 1) / BM) * BM;
        }
        g_offsets[NE] = off;
    }
}

__global__ void scatter_kernel() {
    int i = blockIdx.x * blockDim.x + threadIdx.x;
    if (i >= NTOK * 2) return;
    int e = g_tok_e[i];
    int slot = atomicAdd(&g_cursor[e], 1);
    g_perm[slot] = i >> 1;
    g_wgt[slot]  = g_tok_w[i];
}

// all four weight tensors fp32->fp16 in one launch
__global__ void cvt_w_kernel(const float* __restrict__ sW1,
                             const float* __restrict__ sW2,
                             const float* __restrict__ rW1,
                             const float* __restrict__ rW2) {
    constexpr int N1 = D * HD;
    constexpr int N2 = N1 + HD * D;
    constexpr int N3 = N2 + NE * D * HD;
    constexpr int N4 = N3 + NE * HD * D;
    int i = (blockIdx.x * blockDim.x + threadIdx.x) * 2;
    if (i >= N4) return;
    const float* src;
    __half* dst;
    int off;
    if (i < N1)      { src = sW1; dst = g_W1h; off = i; }
    else if (i < N2) { src = sW2; dst = g_W2h; off = i - N1; }
    else if (i < N3) { src = rW1; dst = g_r1h; off = i - N2; }
    else             { src = rW2; dst = g_r2h; off = i - N3; }
    float2 v = *reinterpret_cast<const float2*>(src + off);
    *reinterpret_cast<__half2*>(dst + off) =
        __halves2half2(__float2half(v.x), __float2half(v.y));
}

__device__ __forceinline__ float silu(float v) { return v / (1.0f + expf(-v)); }

// ---------------- mma helpers ----------------

__device__ __forceinline__ void ldsm4(uint32_t (&r)[4], uint32_t addr) {
    asm volatile("ldmatrix.sync.aligned.m8n8.x4.shared.b16 {%0,%1,%2,%3}, [%4];\n"
        : "=r"(r[0]), "=r"(r[1]), "=r"(r[2]), "=r"(r[3]) : "r"(addr));
}
__device__ __forceinline__ void ldsm4t(uint32_t (&r)[4], uint32_t addr) {
    asm volatile("ldmatrix.sync.aligned.m8n8.x4.trans.shared.b16 {%0,%1,%2,%3}, [%4];\n"
        : "=r"(r[0]), "=r"(r[1]), "=r"(r[2]), "=r"(r[3]) : "r"(addr));
}
__device__ __forceinline__ void mma_f16(float (&c)[4], const uint32_t (&a)[4],
                                        uint32_t b0, uint32_t b1) {
    asm volatile(
        "mma.sync.aligned.m16n8k16.row.col.f32.f16.f16.f32 "
        "{%0,%1,%2,%3}, {%4,%5,%6,%7}, {%8,%9}, {%0,%1,%2,%3};\n"
        : "+f"(c[0]), "+f"(c[1]), "+f"(c[2]), "+f"(c[3])
        : "r"(a[0]), "r"(a[1]), "r"(a[2]), "r"(a[3]), "r"(b0), "r"(b1));
}
__device__ __forceinline__ void red_add_v4(float* p, float a, float b,
                                           float c, float d) {
    asm volatile("red.global.add.v4.f32 [%0], {%1,%2,%3,%4};"
                 :: "l"(p), "f"(a), "f"(b), "f"(c), "f"(d) : "memory");
}

// MODE 0: Hs = silu(X@W1+b)      MODE 1: Hr = silu(X[perm]@rW1[e]+b)
// MODE 2: out = Hs@W2+b (store)  MODE 3: out[tok] += w*(Hr@rW2[e]+b) (vec red)
template <int MODE, int KDIM, int NDIM>
__device__ __forceinline__ void gemm_body(SmemTiles& sm, int rowTile,
                                          const float* __restrict__ bias,
                                          float* __restrict__ out) {
    const int tid = threadIdx.x;
    const int colTile = blockIdx.x * BN;

    const __half* Wp;
    const float* bb = bias;
    if constexpr (MODE == 0)      Wp = g_W1h;
    else if constexpr (MODE == 2) Wp = g_W2h;
    else {
        int e = 0;
#pragma unroll
        for (int i = 1; i < NE; i++) if (rowTile >= g_offsets[i]) e = i;
        size_t off = (size_t)e * KDIM * NDIM;
        if constexpr (MODE == 1) Wp = g_r1h + off;
        else                     Wp = g_r2h + off;
        bb = bias + e * NDIM;
    }
    const __half* Ag;
    if constexpr (MODE <= 1)      Ag = g_Xh;
    else if constexpr (MODE == 2) Ag = g_Hsh;
    else                          Ag = g_Hrh;

    if (tid < BM) {
        int r = rowTile + tid;
        if constexpr (MODE == 1) sm.s_row[tid] = g_perm[r];
        else                     sm.s_row[tid] = r;
        if constexpr (MODE == 3) { sm.s_tok[tid] = g_perm[r]; sm.s_w[tid] = g_wgt[r]; }
    }
    __syncthreads();

    const int lane = tid & 31, warp = tid >> 5;
    const int wm = warp >> 2;     // 0..1 -> 64 rows each
    const int wn = warp & 3;      // 0..3 -> 32 cols each

    // staging: A 128 rows x 32 halfs (2 vec/thread), B 32 rows x 128 halfs
    const int aR0 = tid >> 2,  aC = (tid & 3) * 8;
    const int bR0 = tid >> 4,  bC = (tid & 15) * 8;
    const __half* Ap0 = Ag + (size_t)sm.s_row[aR0] * KDIM + aC;
    const __half* Ap1 = Ag + (size_t)sm.s_row[aR0 + 64] * KDIM + aC;
    const __half* Bp0 = Wp + (size_t)bR0 * NDIM + colTile + bC;
    const __half* Bp1 = Wp + (size_t)(bR0 + 16) * NDIM + colTile + bC;

    uint32_t sAaddr = (uint32_t)__cvta_generic_to_shared(
        &sm.sA[0][wm * 64 + (lane & 15)][(lane >> 4) * 8]);
    uint32_t sBaddr = (uint32_t)__cvta_generic_to_shared(
        &sm.sB[0][(lane & 7) + ((lane >> 3) & 1) * 8][wn * 32 + (lane >> 4) * 8]);
    constexpr uint32_t A_STAGE = 128 * 40 * 2;
    constexpr uint32_t B_STAGE = 32 * 136 * 2;
    constexpr uint32_t A_ROW   = 40 * 2;
    constexpr uint32_t B_ROW   = 136 * 2;

    float acc[4][4][4] = {};
    uint4 rA0, rA1, rB0, rB1;

    rA0 = *reinterpret_cast<const uint4*>(Ap0);
    rA1 = *reinterpret_cast<const uint4*>(Ap1);
    rB0 = *reinterpret_cast<const uint4*>(Bp0);
    rB1 = *reinterpret_cast<const uint4*>(Bp1);
    *reinterpret_cast<uint4*>(&sm.sA[0][aR0][aC])      = rA0;
    *reinterpret_cast<uint4*>(&sm.sA[0][aR0 + 64][aC]) = rA1;
    *reinterpret_cast<uint4*>(&sm.sB[0][bR0][bC])      = rB0;
    *reinterpret_cast<uint4*>(&sm.sB[0][bR0 + 16][bC]) = rB1;
    __syncthreads();

    constexpr int NKT = KDIM / KT;
    int st = 0;
    for (int i = 0; i < NKT; i++) {
        const bool more = (i + 1 < NKT);
        if (more) {
            const int kt = (i + 1) * KT;
            rA0 = *reinterpret_cast<const uint4*>(Ap0 + kt);
            rA1 = *reinterpret_cast<const uint4*>(Ap1 + kt);
            rB0 = *reinterpret_cast<const uint4*>(Bp0 + (size_t)kt * NDIM);
            rB1 = *reinterpret_cast<const uint4*>(Bp1 + (size_t)kt * NDIM);
        }
#pragma unroll
        for (int kk = 0; kk < 2; kk++) {
            uint32_t aF[4][4], bF[2][4];
#pragma unroll
            for (int mi = 0; mi < 4; mi++)
                ldsm4(aF[mi], sAaddr + st * A_STAGE + kk * 32 + mi * (16 * A_ROW));
#pragma unroll
            for (int p = 0; p < 2; p++)
                ldsm4t(bF[p], sBaddr + st * B_STAGE + kk * (16 * B_ROW) + p * 32);
#pragma unroll
            for (int mi = 0; mi < 4; mi++)
#pragma unroll
                for (int ni = 0; ni < 4; ni++) {
                    const int p = ni >> 1, q = (ni & 1) * 2;
                    mma_f16(acc[mi][ni], aF[mi], bF[p][q], bF[p][q + 1]);
                }
        }
        if (more) {
            *reinterpret_cast<uint4*>(&sm.sA[st ^ 1][aR0][aC])      = rA0;
            *reinterpret_cast<uint4*>(&sm.sA[st ^ 1][aR0 + 64][aC]) = rA1;
            *reinterpret_cast<uint4*>(&sm.sB[st ^ 1][bR0][bC])      = rB0;
            *reinterpret_cast<uint4*>(&sm.sB[st ^ 1][bR0 + 16][bC]) = rB1;
        }
        st ^= 1;
        __syncthreads();
    }

    // epilogue
    const int r0 = lane >> 2, c0 = (lane & 3) * 2;
#pragma unroll
    for (int mi = 0; mi < 4; mi++) {
#pragma unroll
        for (int rr = 0; rr < 2; rr++) {
            const int m = wm * 64 + mi * 16 + r0 + rr * 8;
            const int grow = rowTile + m;
#pragma unroll
            for (int ni = 0; ni < 4; ni++) {
                const int col = colTile + wn * 32 + ni * 8 + c0;
                float v0 = acc[mi][ni][rr * 2 + 0] + bb[col];
                float v1 = acc[mi][ni][rr * 2 + 1] + bb[col + 1];
                if constexpr (MODE <= 1) {
                    v0 = silu(v0); v1 = silu(v1);
                    __half* H = (MODE == 0 ? g_Hsh : g_Hrh);
                    *reinterpret_cast<__half2*>(H + (size_t)grow * NDIM + col)
                        = __halves2half2(__float2half(v0), __float2half(v1));
                } else if constexpr (MODE == 2) {
                    *reinterpret_cast<float2*>(out + (size_t)grow * NDIM + col)
                        = make_float2(v0, v1);
                } else {
                    // lane-paired vectorized reduction: even lane covers 4 cols
                    const float w = sm.s_w[m];
                    float a0 = w * v0, a1 = w * v1;
                    float p0 = __shfl_xor_sync(0xffffffffu, a0, 1);
                    float p1 = __shfl_xor_sync(0xffffffffu, a1, 1);
                    if (!(lane & 1)) {
                        const int colv = colTile + wn * 32 + ni * 8 + (lane & 2) * 2;
                        float* dst = out + (size_t)sm.s_tok[m] * NDIM + colv;
                        red_add_v4(dst, a0, a1, p0, p1);
                    }
                }
            }
        }
    }
}

// layer 1 fused: y < YT_S -> shared (MODE 0), else routed (MODE 1).
// Outputs are disjoint (g_Hsh vs g_Hrh) -> safe in one launch.
__global__ void __launch_bounds__(256, 2)
gemm_layer1(const float* __restrict__ sb1, const float* __restrict__ rb1) {
    __shared__ SmemTiles sm;
    const int y = blockIdx.y;
    if (y < YT_S) gemm_body<0, D, HD>(sm, y * BM, sb1, nullptr);
    else          gemm_body<1, D, HD>(sm, (y - YT_S) * BM, rb1, nullptr);
}
// layer 2 split: MODE2 stores must complete before MODE3 reductions (stream order)
__global__ void __launch_bounds__(256, 2)
gemm_l2s(const float* __restrict__ sb2, float* __restrict__ out) {
    __shared__ SmemTiles sm;
    gemm_body<2, HD, D>(sm, blockIdx.y * BM, sb2, out);
}
__global__ void __launch_bounds__(256, 2)
gemm_l2r(const float* __restrict__ rb2, float* __restrict__ out) {
    __shared__ SmemTiles sm;
    gemm_body<3, HD, D>(sm, blockIdx.y * BM, rb2, out);
}

extern "C" void kernel_launch(void* const* d_in, const int* in_sizes, int n_in,
                              void* d_out, int out_size) {
    (void)in_sizes; (void)n_in; (void)out_size;
    const float* X   = (const float*)d_in[0];
    const float* RW  = (const float*)d_in[1];
    const float* EB  = (const float*)d_in[2];
    const float* sW1 = (const float*)d_in[3];
    const float* sb1 = (const float*)d_in[4];
    const float* sW2 = (const float*)d_in[5];
    const float* sb2 = (const float*)d_in[6];
    const float* rW1 = (const float*)d_in[7];
    const float* rb1 = (const float*)d_in[8];
    const float* rW2 = (const float*)d_in[9];
    const float* rb2 = (const float*)d_in[10];
    float* out = (float*)d_out;

    init_kernel<<<(CAP + 255) / 256, 256>>>();
    routing_kernel<<<NTOK / 8, 256>>>(X, RW, EB);
    prefix_kernel<<<1, 32>>>();
    scatter_kernel<<<(NTOK * 2) / 256, 256>>>();

    constexpr int WTOT = D * HD + HD * D + NE * D * HD + NE * HD * D;
    cvt_w_kernel<<<(WTOT / 2 + 255) / 256, 256>>>(sW1, sW2, rW1, rW2);

    gemm_layer1<<<dim3(HD / BN, YT_S + YT_R), 256>>>(sb1, rb1);
    gemm_l2s<<<dim3(D / BN, YT_S), 256>>>(sb2, out);
    gemm_l2r<<<dim3(D / BN, YT_R), 256>>>(rb2, out);
}